// round 9
// baseline (speedup 1.0000x reference)
#include <cuda_runtime.h>
#include <cuda_bf16.h>
#include <cstdint>

#define BB 128
#define TT 256
#define DD 64
#define HH 512
#define NBLK 128
#define NTHR 256
#define PRED_SZ (BB*(TT-1)*DD)

// smem byte layout
#define WBUF_STRIDE 12288            // per-warp: 3 bufs x (2KB hi + 2KB lo)
#define SM_AW 0                      // 8 * 12288 = 98304
#define W1_STRIDE 584
#define W2_STRIDE 1032
#define SM_W1HI 98304
#define SM_W1LO (SM_W1HI + 16*W1_STRIDE*2)   // 116992
#define SM_W2HI (SM_W1LO + 16*W1_STRIDE*2)   // 135680
#define SM_W2LO (SM_W2HI + 16*W2_STRIDE*2)   // 168704
#define SM_WP   (SM_W2LO + 16*W2_STRIDE*2)   // 201728
#define SM_TOTAL (SM_WP + 2048)              // 203776

// h state as PRE-SWIZZLED bf16 hi/lo arrays (ldmatrix tile layout) + fp32 h2 for pred.
__device__ __align__(16) unsigned short g_h1h[2][BB*HH], g_h1l[2][BB*HH];
__device__ __align__(16) unsigned short g_h2h[2][BB*HH], g_h2l[2][BB*HH];
__device__ __align__(16) float g_h2f[2][BB*HH];
__device__ __align__(16) unsigned short g_curh[BB*DD], g_curl[BB*DD];
__device__ unsigned int g_bar;

__device__ __forceinline__ uint32_t smem_u32(const void* p) {
    uint32_t a;
    asm("{ .reg .u64 t; cvta.to.shared.u64 t, %1; cvt.u32.u64 %0, t; }" : "=r"(a) : "l"(p));
    return a;
}
__device__ __forceinline__ void ldsm4(uint32_t r[4], uint32_t addr) {
    asm volatile("ldmatrix.sync.aligned.m8n8.x4.shared.b16 {%0,%1,%2,%3}, [%4];"
        : "=r"(r[0]), "=r"(r[1]), "=r"(r[2]), "=r"(r[3]) : "r"(addr));
}
__device__ __forceinline__ void mma_bf16(float c[4], const uint32_t a[4], uint32_t b0, uint32_t b1) {
    asm volatile("mma.sync.aligned.m16n8k16.row.col.f32.bf16.bf16.f32 "
        "{%0,%1,%2,%3}, {%4,%5,%6,%7}, {%8,%9}, {%0,%1,%2,%3};"
        : "+f"(c[0]), "+f"(c[1]), "+f"(c[2]), "+f"(c[3])
        : "r"(a[0]), "r"(a[1]), "r"(a[2]), "r"(a[3]), "r"(b0), "r"(b1));
}
__device__ __forceinline__ void bf16split(float v, unsigned short &hi, unsigned short &lo) {
    __nv_bfloat16 hb = __float2bfloat16(v);
    hi = __bfloat16_as_ushort(hb);
    lo = __bfloat16_as_ushort(__float2bfloat16(v - __bfloat162float(hb)));
}
__device__ __forceinline__ int hswz(int r, int col) {
    int u = (col >> 3) & 7;
    return r*HH + (col >> 6)*64 + ((u ^ (r & 7)) << 3) + (col & 7);
}
__device__ __forceinline__ int cswz(int r, int col) {
    return r*DD + (((col >> 3) ^ (r & 7)) << 3) + (col & 7);
}

__device__ __forceinline__ void grid_barrier() {
    __syncthreads();
    if (threadIdx.x == 0) {
        __threadfence();
        unsigned my = atomicAdd(&g_bar, 1u) + 1u;
        unsigned target = my + (NBLK - 1u) - ((my - 1u) % NBLK);
        while ((int)(*(volatile unsigned*)&g_bar - target) < 0) __nanosleep(32);
        __threadfence();
    }
    __syncthreads();
}

// Warp-local: copy this warp's 16-row slice of one 64-k chunk (hi+lo) into its ring buffer.
// lane: r_local = lane&15 ; arr = lane>>4 (0=hi,1=lo); each lane copies 128B = 8 x 16B.
__device__ __forceinline__ void cpa_issue(uint32_t bufbase,
        const unsigned short* __restrict__ ghi, const unsigned short* __restrict__ glo,
        int rowElems, int elemOff, int wrow0, int lane) {
    int r_local = lane & 15;
    int arr = lane >> 4;
    const unsigned short* s = (arr ? glo : ghi) + (wrow0 + r_local)*rowElems + elemOff;
    uint32_t d = bufbase + (uint32_t)(arr*2048 + r_local*128);
    #pragma unroll
    for (int i = 0; i < 8; i++) {
        asm volatile("cp.async.cg.shared.global [%0], [%1], 16;"
            :: "r"(d + i*16), "l"(s + i*8) : "memory");
    }
    asm volatile("cp.async.commit_group;" ::: "memory");
}
__device__ __forceinline__ void cpa_wait(int remaining) {
    if (remaining >= 2)      asm volatile("cp.async.wait_group 2;" ::: "memory");
    else if (remaining == 1) asm volatile("cp.async.wait_group 1;" ::: "memory");
    else                     asm volatile("cp.async.wait_group 0;" ::: "memory");
    __syncwarp();
}

// One 64-k chunk of MMAs from this warp's private buffer (hi at +0, lo at +2048).
__device__ __forceinline__ void mma_chunk(float C0h[4], float C0l[4], float C1h[4], float C1l[4],
    uint32_t abase, int lane, uint32_t bhi, uint32_t blo) {
    const uint32_t arow_off = (uint32_t)((lane & 15) * 128);
    const int rsw = lane & 7;
    const int ahalf = (lane >> 4) & 1;
    #pragma unroll
    for (int kk = 0; kk < 4; kk++) {
        uint32_t asw = (uint32_t)(((2*kk + ahalf) ^ rsw) << 4);
        uint32_t ah[4], al[4], bh[4], bl[4];
        ldsm4(ah, abase + arow_off + asw);
        ldsm4(al, abase + 2048 + arow_off + asw);
        ldsm4(bh, bhi + kk*32);
        ldsm4(bl, blo + kk*32);
        mma_bf16(C0h, ah, bh[0], bh[1]);
        mma_bf16(C1h, ah, bh[2], bh[3]);
        mma_bf16(C0l, ah, bl[0], bl[1]);
        mma_bf16(C1l, ah, bl[2], bl[3]);
        mma_bf16(C0l, al, bh[0], bh[1]);
        mma_bf16(C1l, al, bh[2], bh[3]);
    }
}

__device__ __forceinline__ void gates2(const float C0[4], const float C1[4],
    float bi, float bf_, float bg, float bo, float cst[2], float hout[2]) {
    #pragma unroll
    for (int h = 0; h < 2; h++) {
        float zi = C0[2*h] + bi, zf = C0[2*h+1] + bf_;
        float zg = C1[2*h] + bg, zo = C1[2*h+1] + bo;
        float ig = 1.f/(1.f + expf(-zi));
        float fg = 1.f/(1.f + expf(-zf));
        float gg = tanhf(zg);
        float og = 1.f/(1.f + expf(-zo));
        float cn = fg*cst[h] + ig*gg;
        cst[h] = cn;
        hout[h] = og*tanhf(cn);
    }
}

__global__ void __launch_bounds__(NTHR, 1) ajrnn_kernel(
    const float* __restrict__ x,
    const float* __restrict__ k0, const float* __restrict__ r0, const float* __restrict__ b0,
    const float* __restrict__ k1, const float* __restrict__ r1, const float* __restrict__ b1,
    const float* __restrict__ Wm, const float* __restrict__ bias,
    float* __restrict__ out)
{
    extern __shared__ char smem[];
    const uint32_t smb = smem_u32(smem);
    const int tid = threadIdx.x;
    const int bid = blockIdx.x;
    const int n0  = bid * 4;
    const int dcol = bid >> 1;
    const int wid = tid >> 5, lane = tid & 31;
    float* sh_wp = (float*)(smem + SM_WP);

    // ---- weights: fp32 -> bf16 hi/lo, gate-interleaved col order ----
    unsigned short* w1h = (unsigned short*)(smem + SM_W1HI);
    unsigned short* w1l = (unsigned short*)(smem + SM_W1LO);
    unsigned short* w2h = (unsigned short*)(smem + SM_W2HI);
    unsigned short* w2l = (unsigned short*)(smem + SM_W2LO);
    for (int idx = tid; idx < 16*576; idx += NTHR) {
        int p = idx & 15, k = idx >> 4;
        int col = (2*(p>>3) + (p&1))*HH + n0 + ((p&7)>>1);
        float w = (k < DD) ? k0[k*2048 + col] : r0[(k-DD)*2048 + col];
        unsigned short hb, lb; bf16split(w, hb, lb);
        w1h[p*W1_STRIDE + k] = hb;
        w1l[p*W1_STRIDE + k] = lb;
    }
    for (int idx = tid; idx < 16*1024; idx += NTHR) {
        int p = idx & 15, k = idx >> 4;
        int col = (2*(p>>3) + (p&1))*HH + n0 + ((p&7)>>1);
        float w = (k < HH) ? k1[k*2048 + col] : r1[(k-HH)*2048 + col];
        unsigned short hb, lb; bf16split(w, hb, lb);
        w2h[p*W2_STRIDE + k] = hb;
        w2l[p*W2_STRIDE + k] = lb;
    }
    for (int i = tid; i < 512; i += NTHR) sh_wp[i] = Wm[i*DD + dcol];
    // zero global state (128 CTAs x 256 threads, 2 elems each)
    #pragma unroll
    for (int i = 0; i < 2; i++) {
        int gidx = i*NBLK*NTHR + bid*NTHR + tid;
        g_h1h[0][gidx] = 0; g_h1l[0][gidx] = 0;
        g_h2h[0][gidx] = 0; g_h2l[0][gidx] = 0;
        g_h2f[0][gidx] = 0.f;
    }
    const float biasd = bias[dcol];

    const int jj = lane & 3;
    const float bi0 = b0[0*HH + n0 + jj], bf0 = b0[1*HH + n0 + jj];
    const float bg0 = b0[2*HH + n0 + jj], bo0 = b0[3*HH + n0 + jj];
    const float bi1 = b1[0*HH + n0 + jj], bf1 = b1[1*HH + n0 + jj];
    const float bg1 = b1[2*HH + n0 + jj], bo1 = b1[3*HH + n0 + jj];

    // per-warp geometry
    const int wrow0 = wid * 16;                       // this warp's M rows
    const uint32_t wbuf = smb + SM_AW + wid*WBUF_STRIDE;
    const int bn  = (lane & 7) | ((lane >> 1) & 8);
    const int bk8 = (lane >> 3) & 1;
    const uint32_t b1h = smb + SM_W1HI + bn*(W1_STRIDE*2) + bk8*16;
    const uint32_t b1lo = smb + SM_W1LO + bn*(W1_STRIDE*2) + bk8*16;
    const uint32_t b2h = smb + SM_W2HI + bn*(W2_STRIDE*2) + bk8*16;
    const uint32_t b2lo = smb + SM_W2LO + bn*(W2_STRIDE*2) + bk8*16;
    const int crow = wrow0 + (lane >> 2);             // C rows: crow, crow+8

    float c1st[2] = {0.f, 0.f}, c2st[2] = {0.f, 0.f};
    grid_barrier();

    // ---------------- time loop ----------------
    for (int t = 0; t < TT; t++) {
        const int rb = t & 1;
        const int wb = rb ^ 1;

        // ---- Phase A: pred (-> out) + imputed cur ----
        {
            const int r  = ((bid & 1) * 64) + (tid >> 2);
            const int l4 = tid & 3;
            if (t == 0) {
                if (l4 == 0) {
                    float cv = x[(r*TT)*DD + dcol];
                    unsigned short chi, clo; bf16split(cv, chi, clo);
                    int ci = cswz(r, dcol);
                    g_curh[ci] = chi; g_curl[ci] = clo;
                }
            } else {
                const float* hrow = &g_h2f[rb][r*HH + l4*128];
                const float* wv = sh_wp + l4*128;
                float sacc = 0.f;
                #pragma unroll
                for (int kk = 0; kk < 128; kk += 4) {
                    float4 h4 = __ldcg((const float4*)(hrow + kk));
                    sacc += h4.x*wv[kk] + h4.y*wv[kk+1] + h4.z*wv[kk+2] + h4.w*wv[kk+3];
                }
                sacc += __shfl_xor_sync(0xffffffffu, sacc, 2);
                sacc += __shfl_xor_sync(0xffffffffu, sacc, 1);
                if (l4 == 0) {
                    float p  = sacc + biasd;
                    float xv = x[(r*TT + t)*DD + dcol];
                    float cv = (xv == 128.0f) ? p : xv;
                    unsigned short chi, clo; bf16split(cv, chi, clo);
                    int ci = cswz(r, dcol);
                    g_curh[ci] = chi; g_curl[ci] = clo;
                    out[(r*(TT-1) + (t-1))*DD + dcol] = p;
                }
            }
        }
        grid_barrier();

        // ---- Phase B: z = [cur | h1_old] @ W1, 9 chunks, warp-private cp.async ring ----
        {
            float C0h[4]={0,0,0,0}, C0l[4]={0,0,0,0}, C1h[4]={0,0,0,0}, C1l[4]={0,0,0,0};
            // prologue: chunks 0..2
            cpa_issue(wbuf + 0*4096, g_curh, g_curl, DD, 0, wrow0, lane);
            cpa_issue(wbuf + 1*4096, g_h1h[rb], g_h1l[rb], HH, 0, wrow0, lane);
            cpa_issue(wbuf + 2*4096, g_h1h[rb], g_h1l[rb], HH, 64, wrow0, lane);
            #pragma unroll 1
            for (int c = 0; c < 9; c++) {
                cpa_wait(9 - 1 - c);
                mma_chunk(C0h, C0l, C1h, C1l, wbuf + (c % 3)*4096, lane,
                          b1h + c*128, b1lo + c*128);
                if (c + 3 < 9)
                    cpa_issue(wbuf + ((c+3) % 3)*4096, g_h1h[rb], g_h1l[rb], HH, (c+2)*64, wrow0, lane);
            }
            float C0[4], C1[4];
            #pragma unroll
            for (int i = 0; i < 4; i++) { C0[i] = C0h[i] + C0l[i]; C1[i] = C1h[i] + C1l[i]; }
            float hout[2];
            gates2(C0, C1, bi0, bf0, bg0, bo0, c1st, hout);
            #pragma unroll
            for (int h = 0; h < 2; h++) {
                int r = crow + 8*h;
                unsigned short hi, lo; bf16split(hout[h], hi, lo);
                int p = hswz(r, n0 + jj);
                g_h1h[wb][p] = hi; g_h1l[wb][p] = lo;
            }
        }
        grid_barrier();

        // ---- Phase C: z = [h1_new | h2_old] @ W2, 16 chunks ----
        {
            float C0h[4]={0,0,0,0}, C0l[4]={0,0,0,0}, C1h[4]={0,0,0,0}, C1l[4]={0,0,0,0};
            cpa_issue(wbuf + 0*4096, g_h1h[wb], g_h1l[wb], HH, 0, wrow0, lane);
            cpa_issue(wbuf + 1*4096, g_h1h[wb], g_h1l[wb], HH, 64, wrow0, lane);
            cpa_issue(wbuf + 2*4096, g_h1h[wb], g_h1l[wb], HH, 128, wrow0, lane);
            #pragma unroll 1
            for (int c = 0; c < 16; c++) {
                cpa_wait(16 - 1 - c);
                mma_chunk(C0h, C0l, C1h, C1l, wbuf + (c % 3)*4096, lane,
                          b2h + c*128, b2lo + c*128);
                if (c + 3 < 16) {
                    int cc = c + 3;
                    const unsigned short* sh = (cc < 8) ? g_h1h[wb] : g_h2h[rb];
                    const unsigned short* sl = (cc < 8) ? g_h1l[wb] : g_h2l[rb];
                    int off = ((cc < 8) ? cc : (cc - 8)) * 64;
                    cpa_issue(wbuf + (cc % 3)*4096, sh, sl, HH, off, wrow0, lane);
                }
            }
            float C0[4], C1[4];
            #pragma unroll
            for (int i = 0; i < 4; i++) { C0[i] = C0h[i] + C0l[i]; C1[i] = C1h[i] + C1l[i]; }
            float hout[2];
            gates2(C0, C1, bi1, bf1, bg1, bo1, c2st, hout);
            #pragma unroll
            for (int h = 0; h < 2; h++) {
                int r = crow + 8*h;
                unsigned short hi, lo; bf16split(hout[h], hi, lo);
                int p = hswz(r, n0 + jj);
                g_h2h[wb][p] = hi; g_h2l[wb][p] = lo;
                g_h2f[wb][r*HH + n0 + jj] = hout[h];
                if (t == TT-1) out[PRED_SZ + r*HH + n0 + jj] = hout[h];
            }
        }
        grid_barrier();
    }
}

extern "C" void kernel_launch(void* const* d_in, const int* in_sizes, int n_in,
                              void* d_out, int out_size) {
    (void)in_sizes; (void)n_in; (void)out_size;
    const float* x    = (const float*)d_in[0];
    const float* k0   = (const float*)d_in[1];
    const float* r0   = (const float*)d_in[2];
    const float* b0   = (const float*)d_in[3];
    const float* k1   = (const float*)d_in[4];
    const float* r1   = (const float*)d_in[5];
    const float* b1   = (const float*)d_in[6];
    const float* Wm   = (const float*)d_in[7];
    const float* bias = (const float*)d_in[8];
    cudaFuncSetAttribute(ajrnn_kernel, cudaFuncAttributeMaxDynamicSharedMemorySize, SM_TOTAL);
    ajrnn_kernel<<<NBLK, NTHR, SM_TOTAL>>>(x, k0, r0, b0, k1, r1, b1, Wm, bias, (float*)d_out);
}

// round 10
// speedup vs baseline: 1.2670x; 1.2670x over previous
#include <cuda_runtime.h>
#include <cuda_bf16.h>
#include <cstdint>

#define BB 128
#define TT 256
#define DD 64
#define HH 512
#define NBLK 128
#define NTHR 512
#define PRED_SZ (BB*(TT-1)*DD)

// smem byte layout
#define GRP_STRIDE 12288             // per row-group: 3 bufs x (2KB hi + 2KB lo)
#define SM_AW 0                      // 8 * 12288 = 98304
#define W1_STRIDE 584
#define W2_STRIDE 1032
#define SM_W1HI 98304
#define SM_W1LO (SM_W1HI + 16*W1_STRIDE*2)   // 116992
#define SM_W2HI (SM_W1LO + 16*W1_STRIDE*2)   // 135680
#define SM_W2LO (SM_W2HI + 16*W2_STRIDE*2)   // 168704
#define SM_WP   (SM_W2LO + 16*W2_STRIDE*2)   // 201728
#define SM_TOTAL (SM_WP + 2048)              // 203776

// h state as PRE-SWIZZLED bf16 hi/lo arrays (ldmatrix tile layout) + fp32 h2 for pred.
__device__ __align__(16) unsigned short g_h1h[2][BB*HH], g_h1l[2][BB*HH];
__device__ __align__(16) unsigned short g_h2h[2][BB*HH], g_h2l[2][BB*HH];
__device__ __align__(16) float g_h2f[2][BB*HH];
__device__ __align__(16) unsigned short g_curh[BB*DD], g_curl[BB*DD];
__device__ unsigned int g_bar;

__device__ __forceinline__ uint32_t smem_u32(const void* p) {
    uint32_t a;
    asm("{ .reg .u64 t; cvta.to.shared.u64 t, %1; cvt.u32.u64 %0, t; }" : "=r"(a) : "l"(p));
    return a;
}
__device__ __forceinline__ void ldsm4(uint32_t r[4], uint32_t addr) {
    asm volatile("ldmatrix.sync.aligned.m8n8.x4.shared.b16 {%0,%1,%2,%3}, [%4];"
        : "=r"(r[0]), "=r"(r[1]), "=r"(r[2]), "=r"(r[3]) : "r"(addr));
}
__device__ __forceinline__ void ldsm2(uint32_t r[2], uint32_t addr) {
    asm volatile("ldmatrix.sync.aligned.m8n8.x2.shared.b16 {%0,%1}, [%2];"
        : "=r"(r[0]), "=r"(r[1]) : "r"(addr));
}
__device__ __forceinline__ void mma_bf16(float c[4], const uint32_t a[4], uint32_t b0, uint32_t b1) {
    asm volatile("mma.sync.aligned.m16n8k16.row.col.f32.bf16.bf16.f32 "
        "{%0,%1,%2,%3}, {%4,%5,%6,%7}, {%8,%9}, {%0,%1,%2,%3};"
        : "+f"(c[0]), "+f"(c[1]), "+f"(c[2]), "+f"(c[3])
        : "r"(a[0]), "r"(a[1]), "r"(a[2]), "r"(a[3]), "r"(b0), "r"(b1));
}
__device__ __forceinline__ void bf16split(float v, unsigned short &hi, unsigned short &lo) {
    __nv_bfloat16 hb = __float2bfloat16(v);
    hi = __bfloat16_as_ushort(hb);
    lo = __bfloat16_as_ushort(__float2bfloat16(v - __bfloat162float(hb)));
}
__device__ __forceinline__ int hswz(int r, int col) {
    int u = (col >> 3) & 7;
    return r*HH + (col >> 6)*64 + ((u ^ (r & 7)) << 3) + (col & 7);
}
__device__ __forceinline__ int cswz(int r, int col) {
    return r*DD + (((col >> 3) ^ (r & 7)) << 3) + (col & 7);
}

__device__ __forceinline__ void grid_barrier() {
    __syncthreads();
    if (threadIdx.x == 0) {
        __threadfence();
        unsigned my = atomicAdd(&g_bar, 1u) + 1u;
        unsigned target = my + (NBLK - 1u) - ((my - 1u) % NBLK);
        while ((int)(*(volatile unsigned*)&g_bar - target) < 0) __nanosleep(32);
        __threadfence();
    }
    __syncthreads();
}
__device__ __forceinline__ void pair_bar(int id) {
    asm volatile("bar.sync %0, 64;" :: "r"(id) : "memory");
}

// This warp copies ITS half-array (hi or lo) slice of one chunk: 16 rows x 128B.
// lane: r_local = lane>>1, seg = lane&1 -> 64B each = 4 x cp.async 16B.
__device__ __forceinline__ void cpa_issue(uint32_t dst /*buf + h*2048*/,
        const unsigned short* __restrict__ g, int rowElems, int elemOff, int wrow0, int lane) {
    int r_local = lane >> 1, seg = lane & 1;
    const unsigned short* s = g + (wrow0 + r_local)*rowElems + elemOff + seg*32;
    uint32_t d = dst + (uint32_t)(r_local*128 + seg*64);
    #pragma unroll
    for (int i = 0; i < 4; i++) {
        asm volatile("cp.async.cg.shared.global [%0], [%1], 16;"
            :: "r"(d + i*16), "l"(s + i*8) : "memory");
    }
    asm volatile("cp.async.commit_group;" ::: "memory");
}

// One 64-k chunk: hi at abase+0, lo at abase+2048. 12 HMMA into C_h/C_l (n=8).
__device__ __forceinline__ void mma_chunk(float C_h[4], float C_l[4],
    uint32_t abase, int lane, uint32_t bhi, uint32_t blo) {
    const uint32_t arow_off = (uint32_t)((lane & 15) * 128);
    const int rsw = lane & 7;
    const int ahalf = (lane >> 4) & 1;
    #pragma unroll
    for (int kk = 0; kk < 4; kk++) {
        uint32_t asw = (uint32_t)(((2*kk + ahalf) ^ rsw) << 4);
        uint32_t ah[4], al[4], bh[2], bl[2];
        ldsm4(ah, abase + arow_off + asw);
        ldsm4(al, abase + 2048 + arow_off + asw);
        ldsm2(bh, bhi + kk*32);
        ldsm2(bl, blo + kk*32);
        mma_bf16(C_h, ah, bh[0], bh[1]);
        mma_bf16(C_l, ah, bl[0], bl[1]);
        mma_bf16(C_l, al, bh[0], bh[1]);
    }
}

__global__ void __launch_bounds__(NTHR, 1) ajrnn_kernel(
    const float* __restrict__ x,
    const float* __restrict__ k0, const float* __restrict__ r0, const float* __restrict__ b0,
    const float* __restrict__ k1, const float* __restrict__ r1, const float* __restrict__ b1,
    const float* __restrict__ Wm, const float* __restrict__ bias,
    float* __restrict__ out)
{
    extern __shared__ char smem[];
    const uint32_t smb = smem_u32(smem);
    const int tid = threadIdx.x;
    const int bid = blockIdx.x;
    const int n0  = bid * 4;
    const int dcol = bid >> 1;
    const int wid = tid >> 5, lane = tid & 31;
    float* sh_wp = (float*)(smem + SM_WP);

    // ---- weights: fp32 -> bf16 hi/lo; column order: p = h*8 + q, q = 2a+b,
    // gate = 2*(a>>1)+b, unit j = 2h + (a&1), logical col = gate*HH + n0 + j ----
    unsigned short* w1h = (unsigned short*)(smem + SM_W1HI);
    unsigned short* w1l = (unsigned short*)(smem + SM_W1LO);
    unsigned short* w2h = (unsigned short*)(smem + SM_W2HI);
    unsigned short* w2l = (unsigned short*)(smem + SM_W2LO);
    for (int idx = tid; idx < 16*576; idx += NTHR) {
        int p = idx & 15, k = idx >> 4;
        int ph = p >> 3, q = p & 7, a = q >> 1, b = q & 1;
        int col = (2*(a>>1) + b)*HH + n0 + 2*ph + (a & 1);
        float w = (k < DD) ? k0[k*2048 + col] : r0[(k-DD)*2048 + col];
        unsigned short hb, lb; bf16split(w, hb, lb);
        w1h[p*W1_STRIDE + k] = hb;
        w1l[p*W1_STRIDE + k] = lb;
    }
    for (int idx = tid; idx < 16*1024; idx += NTHR) {
        int p = idx & 15, k = idx >> 4;
        int ph = p >> 3, q = p & 7, a = q >> 1, b = q & 1;
        int col = (2*(a>>1) + b)*HH + n0 + 2*ph + (a & 1);
        float w = (k < HH) ? k1[k*2048 + col] : r1[(k-HH)*2048 + col];
        unsigned short hb, lb; bf16split(w, hb, lb);
        w2h[p*W2_STRIDE + k] = hb;
        w2l[p*W2_STRIDE + k] = lb;
    }
    sh_wp[tid] = Wm[tid*DD + dcol];
    {
        int gidx = bid*NTHR + tid;
        g_h1h[0][gidx] = 0; g_h1l[0][gidx] = 0;
        g_h2h[0][gidx] = 0; g_h2l[0][gidx] = 0;
        g_h2f[0][gidx] = 0.f;
    }
    const float biasd = bias[dcol];

    // per-warp geometry
    const int rowgrp = wid & 7;
    const int half   = wid >> 3;               // 0: hi copier + cols h*8.., 1: lo
    const int wrow0  = rowgrp * 16;
    const uint32_t gbuf = smb + SM_AW + rowgrp*GRP_STRIDE;   // 3 bufs x 4KB
    const int barid = 8 + rowgrp;
    // bias regs for epilogue lanes (a = lane&3 < 2): unit = n0 + 2*half + a
    const int aa = lane & 3;
    const int ucol = n0 + 2*half + (aa & 1);   // valid for aa<2; dummy otherwise
    const float bi0 = b0[0*HH + ucol], bf0 = b0[1*HH + ucol];
    const float bg0 = b0[2*HH + ucol], bo0 = b0[3*HH + ucol];
    const float bi1 = b1[0*HH + ucol], bf1 = b1[1*HH + ucol];
    const float bg1 = b1[2*HH + ucol], bo1 = b1[3*HH + ucol];

    // B (weight) lane addressing for ldmatrix.x2: lanes 0-15 give addrs
    const int lidx = lane & 15;
    const int bcol = lidx & 7, bk8 = (lidx >> 3) & 1;
    const uint32_t b1h  = smb + SM_W1HI + (half*8 + bcol)*(W1_STRIDE*2) + bk8*16;
    const uint32_t b1lo = smb + SM_W1LO + (half*8 + bcol)*(W1_STRIDE*2) + bk8*16;
    const uint32_t b2h  = smb + SM_W2HI + (half*8 + bcol)*(W2_STRIDE*2) + bk8*16;
    const uint32_t b2lo = smb + SM_W2LO + (half*8 + bcol)*(W2_STRIDE*2) + bk8*16;
    const int crow = wrow0 + (lane >> 2);      // C rows: crow, crow+8

    float c1st[2] = {0.f, 0.f}, c2st[2] = {0.f, 0.f};
    grid_barrier();

    // ---------------- time loop ----------------
    for (int t = 0; t < TT; t++) {
        const int rb = t & 1;
        const int wb = rb ^ 1;

        // ---- Phase A: pred (-> out) + imputed cur ----
        {
            const int r  = ((bid & 1) * 64) + (tid >> 3);
            const int l8 = tid & 7;
            if (t == 0) {
                if (l8 == 0) {
                    float cv = x[(r*TT)*DD + dcol];
                    unsigned short chi, clo; bf16split(cv, chi, clo);
                    int ci = cswz(r, dcol);
                    g_curh[ci] = chi; g_curl[ci] = clo;
                }
            } else {
                const float* hrow = &g_h2f[rb][r*HH + l8*64];
                const float* wv = sh_wp + l8*64;
                float sacc = 0.f;
                #pragma unroll
                for (int kk = 0; kk < 64; kk += 4) {
                    float4 h4 = __ldcg((const float4*)(hrow + kk));
                    sacc += h4.x*wv[kk] + h4.y*wv[kk+1] + h4.z*wv[kk+2] + h4.w*wv[kk+3];
                }
                sacc += __shfl_xor_sync(0xffffffffu, sacc, 4);
                sacc += __shfl_xor_sync(0xffffffffu, sacc, 2);
                sacc += __shfl_xor_sync(0xffffffffu, sacc, 1);
                if (l8 == 0) {
                    float p  = sacc + biasd;
                    float xv = x[(r*TT + t)*DD + dcol];
                    float cv = (xv == 128.0f) ? p : xv;
                    unsigned short chi, clo; bf16split(cv, chi, clo);
                    int ci = cswz(r, dcol);
                    g_curh[ci] = chi; g_curl[ci] = clo;
                    out[(r*(TT-1) + (t-1))*DD + dcol] = p;
                }
            }
        }
        grid_barrier();

        // ---- Phase B: z = [cur | h1_old] @ W1, 9 chunks ----
        {
            float Ch[4]={0,0,0,0}, Cl[4]={0,0,0,0};
            const unsigned short* curA = half ? g_curl : g_curh;
            const unsigned short* h1A  = half ? g_h1l[rb] : g_h1h[rb];
            const uint32_t myoff = (uint32_t)(half * 2048);
            cpa_issue(gbuf + 0*4096 + myoff, curA, DD, 0, wrow0, lane);
            cpa_issue(gbuf + 1*4096 + myoff, h1A, HH, 0, wrow0, lane);
            #pragma unroll 1
            for (int c = 0; c < 9; c++) {
                if (c < 8) asm volatile("cp.async.wait_group 1;" ::: "memory");
                else       asm volatile("cp.async.wait_group 0;" ::: "memory");
                pair_bar(barid);
                mma_chunk(Ch, Cl, gbuf + (c % 3)*4096, lane, b1h + c*128, b1lo + c*128);
                if (c + 2 < 9)
                    cpa_issue(gbuf + ((c+2) % 3)*4096 + myoff, h1A, HH, (c+1)*64, wrow0, lane);
            }
            float C[4], P[4];
            #pragma unroll
            for (int i = 0; i < 4; i++) C[i] = Ch[i] + Cl[i];
            #pragma unroll
            for (int i = 0; i < 4; i++) P[i] = __shfl_xor_sync(0xffffffffu, C[i], 2);
            if (aa < 2) {
                #pragma unroll
                for (int hsel = 0; hsel < 2; hsel++) {
                    float zi = C[2*hsel] + bi0, zf = C[2*hsel+1] + bf0;
                    float zg = P[2*hsel] + bg0, zo = P[2*hsel+1] + bo0;
                    float ig = 1.f/(1.f + expf(-zi));
                    float fg = 1.f/(1.f + expf(-zf));
                    float gg = tanhf(zg);
                    float og = 1.f/(1.f + expf(-zo));
                    float cn = fg*c1st[hsel] + ig*gg;
                    c1st[hsel] = cn;
                    float hn = og*tanhf(cn);
                    int r = crow + 8*hsel;
                    unsigned short hi, lo; bf16split(hn, hi, lo);
                    int p = hswz(r, ucol);
                    g_h1h[wb][p] = hi; g_h1l[wb][p] = lo;
                }
            }
        }
        grid_barrier();

        // ---- Phase C: z = [h1_new | h2_old] @ W2, 16 chunks ----
        {
            float Ch[4]={0,0,0,0}, Cl[4]={0,0,0,0};
            const unsigned short* h1A = half ? g_h1l[wb] : g_h1h[wb];
            const unsigned short* h2A = half ? g_h2l[rb] : g_h2h[rb];
            const uint32_t myoff = (uint32_t)(half * 2048);
            cpa_issue(gbuf + 0*4096 + myoff, h1A, HH, 0, wrow0, lane);
            cpa_issue(gbuf + 1*4096 + myoff, h1A, HH, 64, wrow0, lane);
            #pragma unroll 1
            for (int c = 0; c < 16; c++) {
                if (c < 15) asm volatile("cp.async.wait_group 1;" ::: "memory");
                else        asm volatile("cp.async.wait_group 0;" ::: "memory");
                pair_bar(barid);
                mma_chunk(Ch, Cl, gbuf + (c % 3)*4096, lane, b2h + c*128, b2lo + c*128);
                if (c + 2 < 16) {
                    int cc = c + 2;
                    const unsigned short* src = (cc < 8) ? h1A : h2A;
                    int off = ((cc < 8) ? cc : (cc - 8)) * 64;
                    cpa_issue(gbuf + (cc % 3)*4096 + myoff, src, HH, off, wrow0, lane);
                }
            }
            float C[4], P[4];
            #pragma unroll
            for (int i = 0; i < 4; i++) C[i] = Ch[i] + Cl[i];
            #pragma unroll
            for (int i = 0; i < 4; i++) P[i] = __shfl_xor_sync(0xffffffffu, C[i], 2);
            if (aa < 2) {
                #pragma unroll
                for (int hsel = 0; hsel < 2; hsel++) {
                    float zi = C[2*hsel] + bi1, zf = C[2*hsel+1] + bf1;
                    float zg = P[2*hsel] + bg1, zo = P[2*hsel+1] + bo1;
                    float ig = 1.f/(1.f + expf(-zi));
                    float fg = 1.f/(1.f + expf(-zf));
                    float gg = tanhf(zg);
                    float og = 1.f/(1.f + expf(-zo));
                    float cn = fg*c2st[hsel] + ig*gg;
                    c2st[hsel] = cn;
                    float hn = og*tanhf(cn);
                    int r = crow + 8*hsel;
                    unsigned short hi, lo; bf16split(hn, hi, lo);
                    int p = hswz(r, ucol);
                    g_h2h[wb][p] = hi; g_h2l[wb][p] = lo;
                    g_h2f[wb][r*HH + ucol] = hn;
                    if (t == TT-1) out[PRED_SZ + r*HH + ucol] = hn;
                }
            }
        }
        grid_barrier();
    }
}

extern "C" void kernel_launch(void* const* d_in, const int* in_sizes, int n_in,
                              void* d_out, int out_size) {
    (void)in_sizes; (void)n_in; (void)out_size;
    const float* x    = (const float*)d_in[0];
    const float* k0   = (const float*)d_in[1];
    const float* r0   = (const float*)d_in[2];
    const float* b0   = (const float*)d_in[3];
    const float* k1   = (const float*)d_in[4];
    const float* r1   = (const float*)d_in[5];
    const float* b1   = (const float*)d_in[6];
    const float* Wm   = (const float*)d_in[7];
    const float* bias = (const float*)d_in[8];
    cudaFuncSetAttribute(ajrnn_kernel, cudaFuncAttributeMaxDynamicSharedMemorySize, SM_TOTAL);
    ajrnn_kernel<<<NBLK, NTHR, SM_TOTAL>>>(x, k0, r0, b0, k1, r1, b1, Wm, bias, (float*)d_out);
}

// round 11
// speedup vs baseline: 1.6805x; 1.3264x over previous
#include <cuda_runtime.h>
#include <cuda_bf16.h>
#include <cstdint>

#define BB 128
#define TT 256
#define DD 64
#define HH 512
#define NBLK 128
#define NTHR 512
#define PRED_SZ (BB*(TT-1)*DD)

// smem: 3 A-buffers (hi 16KB + lo 16KB each), then weights, then Wm column
#define BUF_STRIDE 32768
#define SM_AB 0
#define W1_STRIDE 584
#define W2_STRIDE 1032
#define SM_W1HI 98304
#define SM_W1LO (SM_W1HI + 16*W1_STRIDE*2)   // 116992
#define SM_W2HI (SM_W1LO + 16*W1_STRIDE*2)   // 135680
#define SM_W2LO (SM_W2HI + 16*W2_STRIDE*2)   // 168704
#define SM_WP   (SM_W2LO + 16*W2_STRIDE*2)   // 201728
#define SM_TOTAL (SM_WP + 2048)              // 203776

__device__ __align__(16) unsigned short g_h1h[2][BB*HH], g_h1l[2][BB*HH];
__device__ __align__(16) unsigned short g_h2h[2][BB*HH], g_h2l[2][BB*HH];
__device__ __align__(16) float g_h2f[2][BB*HH];
__device__ __align__(16) unsigned short g_curh[BB*DD], g_curl[BB*DD];
__device__ unsigned int g_bar;
__device__ int g_flagA[NBLK], g_flagB[NBLK], g_flagC[NBLK];

__device__ __forceinline__ uint32_t smem_u32(const void* p) {
    uint32_t a;
    asm("{ .reg .u64 t; cvta.to.shared.u64 t, %1; cvt.u32.u64 %0, t; }" : "=r"(a) : "l"(p));
    return a;
}
__device__ __forceinline__ void ldsm4(uint32_t r[4], uint32_t addr) {
    asm volatile("ldmatrix.sync.aligned.m8n8.x4.shared.b16 {%0,%1,%2,%3}, [%4];"
        : "=r"(r[0]), "=r"(r[1]), "=r"(r[2]), "=r"(r[3]) : "r"(addr));
}
__device__ __forceinline__ void mma_bf16(float c[4], const uint32_t a[4], uint32_t b0, uint32_t b1) {
    asm volatile("mma.sync.aligned.m16n8k16.row.col.f32.bf16.bf16.f32 "
        "{%0,%1,%2,%3}, {%4,%5,%6,%7}, {%8,%9}, {%0,%1,%2,%3};"
        : "+f"(c[0]), "+f"(c[1]), "+f"(c[2]), "+f"(c[3])
        : "r"(a[0]), "r"(a[1]), "r"(a[2]), "r"(a[3]), "r"(b0), "r"(b1));
}
__device__ __forceinline__ void bf16split(float v, unsigned short &hi, unsigned short &lo) {
    __nv_bfloat16 hb = __float2bfloat16(v);
    hi = __bfloat16_as_ushort(hb);
    lo = __bfloat16_as_ushort(__float2bfloat16(v - __bfloat162float(hb)));
}
__device__ __forceinline__ int hswz(int r, int col) {
    int u = (col >> 3) & 7;
    return r*HH + (col >> 6)*64 + ((u ^ (r & 7)) << 3) + (col & 7);
}
__device__ __forceinline__ int cswz(int r, int col) {
    return r*DD + (((col >> 3) ^ (r & 7)) << 3) + (col & 7);
}

// Full grid barrier — used ONCE after init.
__device__ __forceinline__ void grid_barrier() {
    __syncthreads();
    if (threadIdx.x == 0) {
        __threadfence();
        unsigned my = atomicAdd(&g_bar, 1u) + 1u;
        unsigned target = my + (NBLK - 1u) - ((my - 1u) % NBLK);
        while ((int)(*(volatile unsigned*)&g_bar - target) < 0) __nanosleep(32);
        __threadfence();
    }
    __syncthreads();
}

// Producer-side gate: wait until all CTAs' flags >= target. Producers only (256 thr).
__device__ __forceinline__ void prod_wait(int* flags, int target, int stid) {
    if (stid < 128) {
        volatile int* f = (volatile int*)(flags + stid);
        while (*f - target < 0) __nanosleep(32);
    }
    asm volatile("bar.sync 12, 256;" ::: "memory");
    __threadfence();
}

// Producers: copy one [128r x 64k] hi+lo chunk into buffer (hi at +0, lo at +16384).
__device__ __forceinline__ void cpa_issue(uint32_t bufhi,
        const unsigned short* __restrict__ ghi, const unsigned short* __restrict__ glo,
        int rowElems, int elemOff, int stid) {
    #pragma unroll
    for (int q = 0; q < 4; q++) {
        int lin = q*256 + stid;
        int r = lin >> 3, cell = lin & 7;
        int gofs = r*rowElems + elemOff + cell*8;
        uint32_t so = (uint32_t)(r*128 + cell*16);
        asm volatile("cp.async.cg.shared.global [%0], [%1], 16;"
            :: "r"(bufhi + so), "l"(ghi + gofs) : "memory");
        asm volatile("cp.async.cg.shared.global [%0], [%1], 16;"
            :: "r"(bufhi + 16384 + so), "l"(glo + gofs) : "memory");
    }
    asm volatile("cp.async.commit_group;" ::: "memory");
}

// Consumer: one 64-k chunk of MMAs, split accumulators.
__device__ __forceinline__ void mma_chunk(float C0h[4], float C0l[4], float C1h[4], float C1l[4],
    uint32_t a_hi, int lane, uint32_t bhi, uint32_t blo) {
    const uint32_t arow_off = (uint32_t)((lane & 15) * 128);
    const int rsw = lane & 7;
    const int ahalf = (lane >> 4) & 1;
    #pragma unroll
    for (int kk = 0; kk < 4; kk++) {
        uint32_t asw = (uint32_t)(((2*kk + ahalf) ^ rsw) << 4);
        uint32_t ah[4], al[4], bh[4], bl[4];
        ldsm4(ah, a_hi + arow_off + asw);
        ldsm4(al, a_hi + 16384 + arow_off + asw);
        ldsm4(bh, bhi + kk*32);
        ldsm4(bl, blo + kk*32);
        mma_bf16(C0h, ah, bh[0], bh[1]);
        mma_bf16(C1h, ah, bh[2], bh[3]);
        mma_bf16(C0l, ah, bl[0], bl[1]);
        mma_bf16(C1l, ah, bl[2], bl[3]);
        mma_bf16(C0l, al, bh[0], bh[1]);
        mma_bf16(C1l, al, bh[2], bh[3]);
    }
}

__device__ __forceinline__ void gates2(const float C0[4], const float C1[4],
    float bi, float bf_, float bg, float bo, float cst[2], float hout[2]) {
    #pragma unroll
    for (int h = 0; h < 2; h++) {
        float zi = C0[2*h] + bi, zf = C0[2*h+1] + bf_;
        float zg = C1[2*h] + bg, zo = C1[2*h+1] + bo;
        float ig = 1.f/(1.f + expf(-zi));
        float fg = 1.f/(1.f + expf(-zf));
        float gg = tanhf(zg);
        float og = 1.f/(1.f + expf(-zo));
        float cn = fg*cst[h] + ig*gg;
        cst[h] = cn;
        hout[h] = og*tanhf(cn);
    }
}

__global__ void __launch_bounds__(NTHR, 1) ajrnn_kernel(
    const float* __restrict__ x,
    const float* __restrict__ k0, const float* __restrict__ r0, const float* __restrict__ b0,
    const float* __restrict__ k1, const float* __restrict__ r1, const float* __restrict__ b1,
    const float* __restrict__ k1b, const float* __restrict__ bias,
    float* __restrict__ out)
{
    const float* Wm = k1b;
    extern __shared__ char smem[];
    const uint32_t smb = smem_u32(smem);
    const int tid = threadIdx.x;
    const int bid = blockIdx.x;
    const int n0  = bid * 4;
    const int dcol = bid >> 1;
    const int wid = tid >> 5, lane = tid & 31;
    const int stid = tid & 255;               // producer thread id
    const bool producer = (tid < 256);
    float* sh_wp = (float*)(smem + SM_WP);

    // epoch bases (deterministic across replays: every CTA ends each launch
    // with identical flag values; we read our own flag before writing anything)
    const int baseA = *(volatile int*)&g_flagA[bid];
    const int baseB = *(volatile int*)&g_flagB[bid];
    const int baseC = *(volatile int*)&g_flagC[bid];

    // ---- weights: fp32 -> bf16 hi/lo, gate-interleaved col order (as R8) ----
    unsigned short* w1h = (unsigned short*)(smem + SM_W1HI);
    unsigned short* w1l = (unsigned short*)(smem + SM_W1LO);
    unsigned short* w2h = (unsigned short*)(smem + SM_W2HI);
    unsigned short* w2l = (unsigned short*)(smem + SM_W2LO);
    for (int idx = tid; idx < 16*576; idx += NTHR) {
        int p = idx & 15, k = idx >> 4;
        int col = (2*(p>>3) + (p&1))*HH + n0 + ((p&7)>>1);
        float w = (k < DD) ? k0[k*2048 + col] : r0[(k-DD)*2048 + col];
        unsigned short hb, lb; bf16split(w, hb, lb);
        w1h[p*W1_STRIDE + k] = hb;
        w1l[p*W1_STRIDE + k] = lb;
    }
    for (int idx = tid; idx < 16*1024; idx += NTHR) {
        int p = idx & 15, k = idx >> 4;
        int col = (2*(p>>3) + (p&1))*HH + n0 + ((p&7)>>1);
        float w = (k < HH) ? k1[k*2048 + col] : r1[(k-HH)*2048 + col];
        unsigned short hb, lb; bf16split(w, hb, lb);
        w2h[p*W2_STRIDE + k] = hb;
        w2l[p*W2_STRIDE + k] = lb;
    }
    sh_wp[tid] = Wm[tid*DD + dcol];
    {
        int gidx = bid*NTHR + tid;
        g_h1h[0][gidx] = 0; g_h1l[0][gidx] = 0;
        g_h2h[0][gidx] = 0; g_h2l[0][gidx] = 0;
        g_h2f[0][gidx] = 0.f;
    }
    // Phase A(0): cur(0) = x(:,0,:)
    if (tid < 64) {
        int r = (bid & 1)*64 + tid;
        float cv = x[(r*TT)*DD + dcol];
        unsigned short chi, clo; bf16split(cv, chi, clo);
        int ci = cswz(r, dcol);
        g_curh[ci] = chi; g_curl[ci] = clo;
    }
    if (tid == 0) g_flagA[bid] = baseA + 1;
    const float biasd = bias[dcol];

    // consumer constants
    const int cwid = wid - 8;                 // 0..7 for consumers
    const int jj = lane & 3;
    const float bi0 = b0[0*HH + n0 + jj], bf0 = b0[1*HH + n0 + jj];
    const float bg0 = b0[2*HH + n0 + jj], bo0 = b0[3*HH + n0 + jj];
    const float bi1 = b1[0*HH + n0 + jj], bf1 = b1[1*HH + n0 + jj];
    const float bg1 = b1[2*HH + n0 + jj], bo1 = b1[3*HH + n0 + jj];
    const uint32_t a_warp_off = (uint32_t)((cwid & 7) * 16 * 128);
    const int bn  = (lane & 7) | ((lane >> 1) & 8);
    const int bk8 = (lane >> 3) & 1;
    const uint32_t b1hA  = smb + SM_W1HI + bn*(W1_STRIDE*2) + bk8*16;
    const uint32_t b1loA = smb + SM_W1LO + bn*(W1_STRIDE*2) + bk8*16;
    const uint32_t b2hA  = smb + SM_W2HI + bn*(W2_STRIDE*2) + bk8*16;
    const uint32_t b2loA = smb + SM_W2LO + bn*(W2_STRIDE*2) + bk8*16;
    const int crow = (cwid & 7)*16 + (lane >> 2);

    grid_barrier();   // only full grid barrier: init state + cur(0) visible

    // prologue: issue chunks (0,0) and (0,1)  [h1(-1)=zeros chunks]
    if (producer) {
        cpa_issue(smb + SM_AB + 0*BUF_STRIDE, g_h1h[0], g_h1l[0], HH, 0, stid);
        cpa_issue(smb + SM_AB + 1*BUF_STRIDE, g_h1h[0], g_h1l[0], HH, 64, stid);
    }

    float C0h[4], C0l[4], C1h[4], C1l[4];
    float c1st[2] = {0.f, 0.f}, c2st[2] = {0.f, 0.f};
    int c3 = 0, p3 = 2;   // consumer buf = n%3, producer target buf = (n+2)%3

    for (int t = 0; t < TT; t++) {
        const int rb = t & 1;
        const int wb = rb ^ 1;
        #pragma unroll 1
        for (int i = 0; i < 25; i++) {
            if (producer)
                asm volatile("cp.async.wait_group 1;" ::: "memory");
            __syncthreads();

            if (producer) {
                // Phase A(t) at iteration 2 of step t (t>=1)
                if (i == 2 && t >= 1) {
                    prod_wait(g_flagC, baseC + t, stid);      // C-flags(t-1)
                    const int r = (bid & 1)*64 + (stid >> 2);
                    const int l4 = stid & 3;
                    const float* hrow = &g_h2f[rb][r*HH + l4*128];
                    const float* wv = sh_wp + l4*128;
                    float sacc = 0.f;
                    #pragma unroll
                    for (int kk = 0; kk < 128; kk += 4) {
                        float4 h4 = __ldcg((const float4*)(hrow + kk));
                        sacc += h4.x*wv[kk] + h4.y*wv[kk+1] + h4.z*wv[kk+2] + h4.w*wv[kk+3];
                    }
                    sacc += __shfl_xor_sync(0xffffffffu, sacc, 2);
                    sacc += __shfl_xor_sync(0xffffffffu, sacc, 1);
                    if (l4 == 0) {
                        float p  = sacc + biasd;
                        float xv = x[(r*TT + t)*DD + dcol];
                        float cv = (xv == 128.0f) ? p : xv;
                        unsigned short chi, clo; bf16split(cv, chi, clo);
                        int ci = cswz(r, dcol);
                        g_curh[ci] = chi; g_curl[ci] = clo;
                        out[(r*(TT-1) + (t-1))*DD + dcol] = p;
                    }
                    __threadfence();
                    asm volatile("bar.sync 12, 256;" ::: "memory");
                    if (stid == 0) *(volatile int*)&g_flagA[bid] = baseA + t + 1;
                }
                // issue chunk (t2, i2) = stream position n+2
                int i2 = i + 2, t2 = t;
                if (i2 >= 25) { i2 -= 25; t2++; }
                if (t2 < TT) {
                    int rb2 = t2 & 1, wb2 = rb2 ^ 1;
                    if (i2 == 8)       prod_wait(g_flagA, baseA + t2 + 1, stid);
                    else if (i2 == 17) prod_wait(g_flagB, baseB + t2 + 1, stid);
                    const unsigned short *sh, *sl; int rowE, eo;
                    if (i2 <= 7)      { sh = g_h1h[rb2]; sl = g_h1l[rb2]; rowE = HH; eo = i2*64; }
                    else if (i2 == 8) { sh = g_curh;     sl = g_curl;     rowE = DD; eo = 0; }
                    else if (i2 <= 16){ sh = g_h2h[rb2]; sl = g_h2l[rb2]; rowE = HH; eo = (i2-9)*64; }
                    else              { sh = g_h1h[wb2]; sl = g_h1l[wb2]; rowE = HH; eo = (i2-17)*64; }
                    cpa_issue(smb + SM_AB + p3*BUF_STRIDE, sh, sl, rowE, eo, stid);
                }
            } else {
                if (i == 0 || i == 9) {
                    #pragma unroll
                    for (int q = 0; q < 4; q++) { C0h[q]=0.f; C0l[q]=0.f; C1h[q]=0.f; C1l[q]=0.f; }
                }
                uint32_t bh, bl;
                if (i <= 8) {
                    int off = (i == 8) ? 0 : (i + 1)*128;
                    bh = b1hA + off; bl = b1loA + off;
                } else {
                    int off = (i <= 16) ? (i - 1)*128 : (i - 17)*128;
                    bh = b2hA + off; bl = b2loA + off;
                }
                mma_chunk(C0h, C0l, C1h, C1l,
                          smb + SM_AB + c3*BUF_STRIDE + a_warp_off, lane, bh, bl);
                if (i == 8) {
                    // B epilogue: h1(t)
                    float C0[4], C1[4];
                    #pragma unroll
                    for (int q = 0; q < 4; q++) { C0[q] = C0h[q] + C0l[q]; C1[q] = C1h[q] + C1l[q]; }
                    float hout[2];
                    gates2(C0, C1, bi0, bf0, bg0, bo0, c1st, hout);
                    #pragma unroll
                    for (int h = 0; h < 2; h++) {
                        int r = crow + 8*h;
                        unsigned short hi, lo; bf16split(hout[h], hi, lo);
                        int p = hswz(r, n0 + jj);
                        g_h1h[wb][p] = hi; g_h1l[wb][p] = lo;
                    }
                    __threadfence();
                    asm volatile("bar.sync 13, 256;" ::: "memory");
                    if (tid == 256) *(volatile int*)&g_flagB[bid] = baseB + t + 1;
                } else if (i == 24) {
                    // C epilogue: h2(t)
                    float C0[4], C1[4];
                    #pragma unroll
                    for (int q = 0; q < 4; q++) { C0[q] = C0h[q] + C0l[q]; C1[q] = C1h[q] + C1l[q]; }
                    float hout[2];
                    gates2(C0, C1, bi1, bf1, bg1, bo1, c2st, hout);
                    #pragma unroll
                    for (int h = 0; h < 2; h++) {
                        int r = crow + 8*h;
                        unsigned short hi, lo; bf16split(hout[h], hi, lo);
                        int p = hswz(r, n0 + jj);
                        g_h2h[wb][p] = hi; g_h2l[wb][p] = lo;
                        g_h2f[wb][r*HH + n0 + jj] = hout[h];
                        if (t == TT-1) out[PRED_SZ + r*HH + n0 + jj] = hout[h];
                    }
                    __threadfence();
                    asm volatile("bar.sync 13, 256;" ::: "memory");
                    if (tid == 256) *(volatile int*)&g_flagC[bid] = baseC + t + 1;
                }
            }
            c3++; if (c3 == 3) c3 = 0;
            p3++; if (p3 == 3) p3 = 0;
        }
    }
}

extern "C" void kernel_launch(void* const* d_in, const int* in_sizes, int n_in,
                              void* d_out, int out_size) {
    (void)in_sizes; (void)n_in; (void)out_size;
    const float* x    = (const float*)d_in[0];
    const float* k0   = (const float*)d_in[1];
    const float* r0   = (const float*)d_in[2];
    const float* b0   = (const float*)d_in[3];
    const float* k1   = (const float*)d_in[4];
    const float* r1   = (const float*)d_in[5];
    const float* b1   = (const float*)d_in[6];
    const float* Wm   = (const float*)d_in[7];
    const float* bias = (const float*)d_in[8];
    cudaFuncSetAttribute(ajrnn_kernel, cudaFuncAttributeMaxDynamicSharedMemorySize, SM_TOTAL);
    ajrnn_kernel<<<NBLK, NTHR, SM_TOTAL>>>(x, k0, r0, b0, k1, r1, b1, Wm, bias, (float*)d_out);
}

// round 12
// speedup vs baseline: 2.0428x; 1.2156x over previous
#include <cuda_runtime.h>
#include <cuda_bf16.h>
#include <cstdint>

#define BB 128
#define TT 256
#define DD 64
#define HH 512
#define NBLK 128
#define NTHR 256
#define PRED_SZ (BB*(TT-1)*DD)

// smem: weights only (bf16 hi/lo) + Wm column
#define W1_STRIDE 584
#define W2_STRIDE 1032
#define SM_W1HI 0
#define SM_W1LO (SM_W1HI + 16*W1_STRIDE*2)
#define SM_W2HI (SM_W1LO + 16*W1_STRIDE*2)
#define SM_W2LO (SM_W2HI + 16*W2_STRIDE*2)
#define SM_WP   (SM_W2LO + 16*W2_STRIDE*2)
#define SM_TOTAL (SM_WP + 2048)

// h state stored in GLOBAL MEMORY in mma-fragment layout:
// tile (rb = row/16, kt = col/16): 32 lanes x 16B; lane's 16B = {a0,a1,a2,a3} bf16x2 regs.
__device__ __align__(16) unsigned short g_h1h[2][BB*HH], g_h1l[2][BB*HH];
__device__ __align__(16) unsigned short g_h2h[2][BB*HH], g_h2l[2][BB*HH];
__device__ __align__(16) float g_h2f[2][BB*HH];
__device__ __align__(16) unsigned short g_curh[BB*DD], g_curl[BB*DD];
__device__ unsigned int g_bar;
__device__ int g_cntA, g_cntB, g_cntC;   // reset to 0 at end of every launch

__device__ __forceinline__ uint32_t smem_u32(const void* p) {
    uint32_t a;
    asm("{ .reg .u64 t; cvta.to.shared.u64 t, %1; cvt.u32.u64 %0, t; }" : "=r"(a) : "l"(p));
    return a;
}
__device__ __forceinline__ void ldsm4(uint32_t r[4], uint32_t addr) {
    asm volatile("ldmatrix.sync.aligned.m8n8.x4.shared.b16 {%0,%1,%2,%3}, [%4];"
        : "=r"(r[0]), "=r"(r[1]), "=r"(r[2]), "=r"(r[3]) : "r"(addr));
}
__device__ __forceinline__ void mma_bf16(float c[4], const uint32_t a[4], uint32_t b0, uint32_t b1) {
    asm volatile("mma.sync.aligned.m16n8k16.row.col.f32.bf16.bf16.f32 "
        "{%0,%1,%2,%3}, {%4,%5,%6,%7}, {%8,%9}, {%0,%1,%2,%3};"
        : "+f"(c[0]), "+f"(c[1]), "+f"(c[2]), "+f"(c[3])
        : "r"(a[0]), "r"(a[1]), "r"(a[2]), "r"(a[3]), "r"(b0), "r"(b1));
}
__device__ __forceinline__ void bf16split(float v, unsigned short &hi, unsigned short &lo) {
    __nv_bfloat16 hb = __float2bfloat16(v);
    hi = __bfloat16_as_ushort(hb);
    lo = __bfloat16_as_ushort(__float2bfloat16(v - __bfloat162float(hb)));
}
// fragment flat index (ushort units) for h arrays (512 cols => 32 kt per row-block)
__device__ __forceinline__ int hfrag_idx(int r, int c) {
    int rb = r >> 4, kt = c >> 4;
    int l = ((r & 7) << 2) | ((c >> 1) & 3);
    int j = ((r >> 3) & 1) | (((c >> 3) & 1) << 1);
    return (((rb*32 + kt)*32 + l) << 3) + j*2 + (c & 1);
}
// cur (64 cols => 4 kt)
__device__ __forceinline__ int cfrag_idx(int r, int c) {
    int rb = r >> 4, kt = c >> 4;
    int l = ((r & 7) << 2) | ((c >> 1) & 3);
    int j = ((r >> 3) & 1) | (((c >> 3) & 1) << 1);
    return (((rb*4 + kt)*32 + l) << 3) + j*2 + (c & 1);
}

__device__ __forceinline__ void grid_barrier() {
    __syncthreads();
    if (threadIdx.x == 0) {
        __threadfence();
        unsigned my = atomicAdd(&g_bar, 1u) + 1u;
        unsigned target = my + (NBLK - 1u) - ((my - 1u) % NBLK);
        while ((int)(*(volatile unsigned*)&g_bar - target) < 0) __nanosleep(32);
        __threadfence();
    }
    __syncthreads();
}

__device__ __forceinline__ void poll_cnt(int* cnt, int target) {
    if ((threadIdx.x & 31) == 0) {
        volatile int* c = (volatile int*)cnt;
        while (*c < target) __nanosleep(64);
    }
    __syncwarp();
    __threadfence();
}

// load one 64-k chunk of A fragments (hi+lo) into registers via LDG.128.cg
__device__ __forceinline__ void issue_chunk(uint4 Ah[4], uint4 Al[4],
    const unsigned short* __restrict__ gh, const unsigned short* __restrict__ gl,
    int nkt, int ktb, int rowgrp, int lane) {
    const uint4* ph = (const uint4*)gh + ((rowgrp*nkt + ktb)*32 + lane);
    const uint4* pl = (const uint4*)gl + ((rowgrp*nkt + ktb)*32 + lane);
    #pragma unroll
    for (int i = 0; i < 4; i++) { Ah[i] = __ldcg(ph + i*32); Al[i] = __ldcg(pl + i*32); }
}

// one 64-k chunk of MMAs: A from registers, B (weights) from smem
__device__ __forceinline__ void compute_chunk(float X0h[4], float X0l[4], float X1h[4], float X1l[4],
    const uint4 Ah[4], const uint4 Al[4], uint32_t bh_addr, uint32_t bl_addr) {
    #pragma unroll
    for (int kk = 0; kk < 4; kk++) {
        uint32_t bh[4], bl[4];
        ldsm4(bh, bh_addr + kk*32);
        ldsm4(bl, bl_addr + kk*32);
        const uint32_t* ah = (const uint32_t*)&Ah[kk];
        const uint32_t* al = (const uint32_t*)&Al[kk];
        mma_bf16(X0h, ah, bh[0], bh[1]);
        mma_bf16(X1h, ah, bh[2], bh[3]);
        mma_bf16(X0l, ah, bl[0], bl[1]);
        mma_bf16(X1l, ah, bl[2], bl[3]);
        mma_bf16(X0l, al, bh[0], bh[1]);
        mma_bf16(X1l, al, bh[2], bh[3]);
    }
}

__device__ __forceinline__ void gates2(const float C0[4], const float C1[4],
    float bi, float bf_, float bg, float bo, float cst[2], float hout[2]) {
    #pragma unroll
    for (int h = 0; h < 2; h++) {
        float zi = C0[2*h] + bi, zf = C0[2*h+1] + bf_;
        float zg = C1[2*h] + bg, zo = C1[2*h+1] + bo;
        float ig = 1.f/(1.f + expf(-zi));
        float fg = 1.f/(1.f + expf(-zf));
        float gg = tanhf(zg);
        float og = 1.f/(1.f + expf(-zo));
        float cn = fg*cst[h] + ig*gg;
        cst[h] = cn;
        hout[h] = og*tanhf(cn);
    }
}

__global__ void __launch_bounds__(NTHR, 1) ajrnn_kernel(
    const float* __restrict__ x,
    const float* __restrict__ k0, const float* __restrict__ r0, const float* __restrict__ b0,
    const float* __restrict__ k1, const float* __restrict__ r1, const float* __restrict__ b1,
    const float* __restrict__ Wm, const float* __restrict__ bias,
    float* __restrict__ out)
{
    extern __shared__ char smem[];
    const uint32_t smb = smem_u32(smem);
    const int tid = threadIdx.x;
    const int bid = blockIdx.x;
    const int n0  = bid * 4;
    const int dcol = bid >> 1;
    const int wid = tid >> 5, lane = tid & 31;
    float* sh_wp = (float*)(smem + SM_WP);

    // ---- weights: fp32 -> bf16 hi/lo, gate-interleaved col order ----
    unsigned short* w1h = (unsigned short*)(smem + SM_W1HI);
    unsigned short* w1l = (unsigned short*)(smem + SM_W1LO);
    unsigned short* w2h = (unsigned short*)(smem + SM_W2HI);
    unsigned short* w2l = (unsigned short*)(smem + SM_W2LO);
    for (int idx = tid; idx < 16*576; idx += NTHR) {
        int p = idx & 15, k = idx >> 4;
        int col = (2*(p>>3) + (p&1))*HH + n0 + ((p&7)>>1);
        float w = (k < DD) ? k0[k*2048 + col] : r0[(k-DD)*2048 + col];
        unsigned short hb, lb; bf16split(w, hb, lb);
        w1h[p*W1_STRIDE + k] = hb;
        w1l[p*W1_STRIDE + k] = lb;
    }
    for (int idx = tid; idx < 16*1024; idx += NTHR) {
        int p = idx & 15, k = idx >> 4;
        int col = (2*(p>>3) + (p&1))*HH + n0 + ((p&7)>>1);
        float w = (k < HH) ? k1[k*2048 + col] : r1[(k-HH)*2048 + col];
        unsigned short hb, lb; bf16split(w, hb, lb);
        w2h[p*W2_STRIDE + k] = hb;
        w2l[p*W2_STRIDE + k] = lb;
    }
    for (int i = tid; i < 512; i += NTHR) sh_wp[i] = Wm[i*DD + dcol];
    // zero global state (parity 0): 128 CTAs x 256 thr x 2
    #pragma unroll
    for (int i = 0; i < 2; i++) {
        int g = i*(NBLK*NTHR) + bid*NTHR + tid;
        g_h1h[0][g] = 0; g_h1l[0][g] = 0;
        g_h2h[0][g] = 0; g_h2l[0][g] = 0;
        g_h2f[0][g] = 0.f;
    }
    // cur(0) = x[:, 0, :] (this CTA's 64-row half, col dcol)
    if (tid < 64) {
        int r = (bid & 1)*64 + tid;
        float cv = x[(r*TT)*DD + dcol];
        unsigned short chi, clo; bf16split(cv, chi, clo);
        int ci = cfrag_idx(r, dcol);
        g_curh[ci] = chi; g_curl[ci] = clo;
    }
    if (tid == 0) atomicAdd(&g_cntA, 1);
    const float biasd = bias[dcol];

    const int jj = lane & 3;
    const float bi0 = b0[0*HH + n0 + jj], bf0 = b0[1*HH + n0 + jj];
    const float bg0 = b0[2*HH + n0 + jj], bo0 = b0[3*HH + n0 + jj];
    const float bi1 = b1[0*HH + n0 + jj], bf1 = b1[1*HH + n0 + jj];
    const float bg1 = b1[2*HH + n0 + jj], bo1 = b1[3*HH + n0 + jj];

    const int rowgrp = wid;                         // 8 warps x 16 rows
    const int crow = rowgrp*16 + (lane >> 2);
    const int bn  = (lane & 7) | ((lane >> 1) & 8);
    const int bk8 = (lane >> 3) & 1;
    const uint32_t b1hA  = smb + SM_W1HI + bn*(W1_STRIDE*2) + bk8*16;
    const uint32_t b1loA = smb + SM_W1LO + bn*(W1_STRIDE*2) + bk8*16;
    const uint32_t b2hA  = smb + SM_W2HI + bn*(W2_STRIDE*2) + bk8*16;
    const uint32_t b2loA = smb + SM_W2LO + bn*(W2_STRIDE*2) + bk8*16;

    grid_barrier();   // init + cur(0) visible everywhere; counters: cntA == 128

    uint4 Ahi[3][4], Alo[3][4];
    float c1st[2] = {0.f, 0.f}, c2st[2] = {0.f, 0.f};

    // prologue: chunks 0,1,2 of step 0 (h1old = zeros array, parity 0)
    issue_chunk(Ahi[0], Alo[0], g_h1h[0], g_h1l[0], 32, 0, rowgrp, lane);
    issue_chunk(Ahi[1], Alo[1], g_h1h[0], g_h1l[0], 32, 4, rowgrp, lane);
    issue_chunk(Ahi[2], Alo[2], g_h1h[0], g_h1l[0], 32, 8, rowgrp, lane);

    for (int t = 0; t < TT; t++) {
        const int rb = t & 1, wb = rb ^ 1;
        const unsigned short *h1r_h = g_h1h[rb], *h1r_l = g_h1l[rb];
        const unsigned short *h2r_h = g_h2h[rb], *h2r_l = g_h2l[rb];
        unsigned short *h1w_h = g_h1h[wb], *h1w_l = g_h1l[wb];
        unsigned short *h2w_h = g_h2h[wb], *h2w_l = g_h2l[wb];
        float B0h[4]={0,0,0,0}, B0l[4]={0,0,0,0}, B1h[4]={0,0,0,0}, B1l[4]={0,0,0,0};
        float D0h[4]={0,0,0,0}, D0l[4]={0,0,0,0}, D1h[4]={0,0,0,0}, D1l[4]={0,0,0,0};

        #pragma unroll
        for (int c = 0; c < 25; c++) {
            const int s = c % 3;
            // ---- compute chunk c ----
            if (c <= 7)
                compute_chunk(B0h,B0l,B1h,B1l, Ahi[s], Alo[s], b1hA + (64 + c*64)*2, b1loA + (64 + c*64)*2);
            else if (c <= 15)
                compute_chunk(D0h,D0l,D1h,D1l, Ahi[s], Alo[s], b2hA + (512 + (c-8)*64)*2, b2loA + (512 + (c-8)*64)*2);
            else if (c == 16)
                compute_chunk(B0h,B0l,B1h,B1l, Ahi[s], Alo[s], b1hA, b1loA);
            else
                compute_chunk(D0h,D0l,D1h,D1l, Ahi[s], Alo[s], b2hA + ((c-17)*64)*2, b2loA + ((c-17)*64)*2);

            // ---- events + issue chunk c+3 (slot just freed) ----
            if (c == 13) {
                if (t > 0) {
                    // Phase A(t): pred from h2f(t-1) (gated by cntC poll at c==5), impute cur(t)
                    const int r  = (bid & 1)*64 + (tid >> 2);
                    const int l4 = tid & 3;
                    const float* hrow = &g_h2f[rb][r*HH + l4*128];
                    const float* wv = sh_wp + l4*128;
                    float sacc = 0.f;
                    #pragma unroll
                    for (int kk = 0; kk < 128; kk += 4) {
                        float4 h4 = __ldcg((const float4*)(hrow + kk));
                        sacc += h4.x*wv[kk] + h4.y*wv[kk+1] + h4.z*wv[kk+2] + h4.w*wv[kk+3];
                    }
                    sacc += __shfl_xor_sync(0xffffffffu, sacc, 2);
                    sacc += __shfl_xor_sync(0xffffffffu, sacc, 1);
                    if (l4 == 0) {
                        float p  = sacc + biasd;
                        float xv = x[(r*TT + t)*DD + dcol];
                        float cv = (xv == 128.0f) ? p : xv;
                        unsigned short chi, clo; bf16split(cv, chi, clo);
                        int ci = cfrag_idx(r, dcol);
                        g_curh[ci] = chi; g_curl[ci] = clo;
                        out[(r*(TT-1) + (t-1))*DD + dcol] = p;
                    }
                    __syncthreads();
                    if (tid == 0) { __threadfence(); atomicAdd(&g_cntA, 1); }
                }
                poll_cnt(&g_cntA, 128*(t+1));
                issue_chunk(Ahi[1], Alo[1], g_curh, g_curl, 4, 0, rowgrp, lane);   // chunk 16
            } else if (c == 16) {
                // ---- B epilogue: h1(t) ----
                float C0[4], C1[4];
                #pragma unroll
                for (int q = 0; q < 4; q++) { C0[q] = B0h[q] + B0l[q]; C1[q] = B1h[q] + B1l[q]; }
                float hout[2];
                gates2(C0, C1, bi0, bf0, bg0, bo0, c1st, hout);
                #pragma unroll
                for (int h = 0; h < 2; h++) {
                    int r = crow + 8*h;
                    unsigned short hi, lo; bf16split(hout[h], hi, lo);
                    int p = hfrag_idx(r, n0 + jj);
                    h1w_h[p] = hi; h1w_l[p] = lo;
                }
                __syncthreads();
                if (tid == 0) { __threadfence(); atomicAdd(&g_cntB, 1); }
                poll_cnt(&g_cntB, 128*(t+1));
                issue_chunk(Ahi[2], Alo[2], h1w_h, h1w_l, 32, 0, rowgrp, lane);  // 17
                issue_chunk(Ahi[0], Alo[0], h1w_h, h1w_l, 32, 4, rowgrp, lane);  // 18
                issue_chunk(Ahi[1], Alo[1], h1w_h, h1w_l, 32, 8, rowgrp, lane);  // 19
            } else if (c <= 12) {
                const int n = c + 3;
                if (n <= 7) {
                    issue_chunk(Ahi[n % 3], Alo[n % 3], h1r_h, h1r_l, 32, n*4, rowgrp, lane);
                } else {
                    if (c == 5) poll_cnt(&g_cntC, 128*t);
                    issue_chunk(Ahi[n % 3], Alo[n % 3], h2r_h, h2r_l, 32, (n-8)*4, rowgrp, lane);
                }
            } else if (c >= 17 && c <= 21) {
                const int n = c + 3;
                issue_chunk(Ahi[n % 3], Alo[n % 3], h1w_h, h1w_l, 32, (n-17)*4, rowgrp, lane);
            }
            // c == 14, 15, 22, 23, 24: no issue
        }

        // ---- C epilogue: h2(t) ----
        {
            float C0[4], C1[4];
            #pragma unroll
            for (int q = 0; q < 4; q++) { C0[q] = D0h[q] + D0l[q]; C1[q] = D1h[q] + D1l[q]; }
            float hout[2];
            gates2(C0, C1, bi1, bf1, bg1, bo1, c2st, hout);
            #pragma unroll
            for (int h = 0; h < 2; h++) {
                int r = crow + 8*h;
                unsigned short hi, lo; bf16split(hout[h], hi, lo);
                int p = hfrag_idx(r, n0 + jj);
                h2w_h[p] = hi; h2w_l[p] = lo;
                g_h2f[wb][r*HH + n0 + jj] = hout[h];
                if (t == TT-1) out[PRED_SZ + r*HH + n0 + jj] = hout[h];
            }
            __syncthreads();
            if (tid == 0) { __threadfence(); atomicAdd(&g_cntC, 1); }
        }
        // refill pipeline for step t+1 (h1old(t+1) = h1(t), gate already passed at c==16)
        if (t + 1 < TT) {
            issue_chunk(Ahi[0], Alo[0], h1w_h, h1w_l, 32, 0, rowgrp, lane);
            issue_chunk(Ahi[1], Alo[1], h1w_h, h1w_l, 32, 4, rowgrp, lane);
            issue_chunk(Ahi[2], Alo[2], h1w_h, h1w_l, 32, 8, rowgrp, lane);
        }
    }

    grid_barrier();
    if (bid == 0 && tid == 0) { g_cntA = 0; g_cntB = 0; g_cntC = 0; }
}

extern "C" void kernel_launch(void* const* d_in, const int* in_sizes, int n_in,
                              void* d_out, int out_size) {
    (void)in_sizes; (void)n_in; (void)out_size;
    const float* x    = (const float*)d_in[0];
    const float* k0   = (const float*)d_in[1];
    const float* r0   = (const float*)d_in[2];
    const float* b0   = (const float*)d_in[3];
    const float* k1   = (const float*)d_in[4];
    const float* r1   = (const float*)d_in[5];
    const float* b1   = (const float*)d_in[6];
    const float* Wm   = (const float*)d_in[7];
    const float* bias = (const float*)d_in[8];
    cudaFuncSetAttribute(ajrnn_kernel, cudaFuncAttributeMaxDynamicSharedMemorySize, SM_TOTAL);
    ajrnn_kernel<<<NBLK, NTHR, SM_TOTAL>>>(x, k0, r0, b0, k1, r1, b1, Wm, bias, (float*)d_out);
}

// round 13
// speedup vs baseline: 2.1508x; 1.0529x over previous
#include <cuda_runtime.h>
#include <cuda_bf16.h>
#include <cstdint>

#define BB 128
#define TT 256
#define DD 64
#define HH 512
#define NBLK 128
#define NTHR 256
#define PRED_SZ (BB*(TT-1)*DD)

// smem: weights only (bf16 hi/lo) + Wm column
#define W1_STRIDE 584
#define W2_STRIDE 1032
#define SM_W1HI 0
#define SM_W1LO (SM_W1HI + 16*W1_STRIDE*2)
#define SM_W2HI (SM_W1LO + 16*W1_STRIDE*2)
#define SM_W2LO (SM_W2HI + 16*W2_STRIDE*2)
#define SM_WP   (SM_W2LO + 16*W2_STRIDE*2)
#define SM_TOTAL (SM_WP + 2048)

// h state in GLOBAL MEMORY in mma-fragment layout.
__device__ __align__(16) unsigned short g_h1h[2][BB*HH], g_h1l[2][BB*HH];
__device__ __align__(16) unsigned short g_h2h[2][BB*HH], g_h2l[2][BB*HH];
__device__ __align__(16) float g_h2f[2][BB*HH];
__device__ __align__(16) unsigned short g_curh[BB*DD], g_curl[BB*DD];
__device__ unsigned int g_bar;
__device__ int g_cntA, g_cntB, g_cntC;   // reset to 0 at end of every launch

__device__ __forceinline__ uint32_t smem_u32(const void* p) {
    uint32_t a;
    asm("{ .reg .u64 t; cvta.to.shared.u64 t, %1; cvt.u32.u64 %0, t; }" : "=r"(a) : "l"(p));
    return a;
}
__device__ __forceinline__ void ldsm4(uint32_t r[4], uint32_t addr) {
    asm volatile("ldmatrix.sync.aligned.m8n8.x4.shared.b16 {%0,%1,%2,%3}, [%4];"
        : "=r"(r[0]), "=r"(r[1]), "=r"(r[2]), "=r"(r[3]) : "r"(addr));
}
__device__ __forceinline__ void mma_bf16(float c[4], const uint32_t a[4], uint32_t b0, uint32_t b1) {
    asm volatile("mma.sync.aligned.m16n8k16.row.col.f32.bf16.bf16.f32 "
        "{%0,%1,%2,%3}, {%4,%5,%6,%7}, {%8,%9}, {%0,%1,%2,%3};"
        : "+f"(c[0]), "+f"(c[1]), "+f"(c[2]), "+f"(c[3])
        : "r"(a[0]), "r"(a[1]), "r"(a[2]), "r"(a[3]), "r"(b0), "r"(b1));
}
__device__ __forceinline__ void bf16split(float v, unsigned short &hi, unsigned short &lo) {
    __nv_bfloat16 hb = __float2bfloat16(v);
    hi = __bfloat16_as_ushort(hb);
    lo = __bfloat16_as_ushort(__float2bfloat16(v - __bfloat162float(hb)));
}
__device__ __forceinline__ int hfrag_idx(int r, int c) {
    int rb = r >> 4, kt = c >> 4;
    int l = ((r & 7) << 2) | ((c >> 1) & 3);
    int j = ((r >> 3) & 1) | (((c >> 3) & 1) << 1);
    return (((rb*32 + kt)*32 + l) << 3) + j*2 + (c & 1);
}
__device__ __forceinline__ int cfrag_idx(int r, int c) {
    int rb = r >> 4, kt = c >> 4;
    int l = ((r & 7) << 2) | ((c >> 1) & 3);
    int j = ((r >> 3) & 1) | (((c >> 3) & 1) << 1);
    return (((rb*4 + kt)*32 + l) << 3) + j*2 + (c & 1);
}

__device__ __forceinline__ void grid_barrier() {
    __syncthreads();
    if (threadIdx.x == 0) {
        __threadfence();
        unsigned my = atomicAdd(&g_bar, 1u) + 1u;
        unsigned target = my + (NBLK - 1u) - ((my - 1u) % NBLK);
        while ((int)(*(volatile unsigned*)&g_bar - target) < 0) __nanosleep(32);
        __threadfence();
    }
    __syncthreads();
}

__device__ __forceinline__ void poll_cnt(int* cnt, int target) {
    if ((threadIdx.x & 31) == 0) {
        volatile int* c = (volatile int*)cnt;
        while (*c < target) __nanosleep(64);
    }
    __syncwarp();
    __threadfence();
}

// load one 64-k chunk of A fragments (hi+lo) into registers via LDG.128.cg
__device__ __forceinline__ void issue_chunk(uint4 Ah[4], uint4 Al[4],
    const unsigned short* __restrict__ gh, const unsigned short* __restrict__ gl,
    int nkt, int ktb, int rowgrp, int lane) {
    const uint4* ph = (const uint4*)gh + ((rowgrp*nkt + ktb)*32 + lane);
    const uint4* pl = (const uint4*)gl + ((rowgrp*nkt + ktb)*32 + lane);
    #pragma unroll
    for (int i = 0; i < 4; i++) { Ah[i] = __ldcg(ph + i*32); Al[i] = __ldcg(pl + i*32); }
}

__device__ __forceinline__ void compute_chunk(float X0h[4], float X0l[4], float X1h[4], float X1l[4],
    const uint4 Ah[4], const uint4 Al[4], uint32_t bh_addr, uint32_t bl_addr) {
    #pragma unroll
    for (int kk = 0; kk < 4; kk++) {
        uint32_t bh[4], bl[4];
        ldsm4(bh, bh_addr + kk*32);
        ldsm4(bl, bl_addr + kk*32);
        const uint32_t* ah = (const uint32_t*)&Ah[kk];
        const uint32_t* al = (const uint32_t*)&Al[kk];
        mma_bf16(X0h, ah, bh[0], bh[1]);
        mma_bf16(X1h, ah, bh[2], bh[3]);
        mma_bf16(X0l, ah, bl[0], bl[1]);
        mma_bf16(X1l, ah, bl[2], bl[3]);
        mma_bf16(X0l, al, bh[0], bh[1]);
        mma_bf16(X1l, al, bh[2], bh[3]);
    }
}

__device__ __forceinline__ void gates2(const float C0[4], const float C1[4],
    float bi, float bf_, float bg, float bo, float cst[2], float hout[2]) {
    #pragma unroll
    for (int h = 0; h < 2; h++) {
        float zi = C0[2*h] + bi, zf = C0[2*h+1] + bf_;
        float zg = C1[2*h] + bg, zo = C1[2*h+1] + bo;
        float ig = 1.f/(1.f + expf(-zi));
        float fg = 1.f/(1.f + expf(-zf));
        float gg = tanhf(zg);
        float og = 1.f/(1.f + expf(-zo));
        float cn = fg*cst[h] + ig*gg;
        cst[h] = cn;
        hout[h] = og*tanhf(cn);
    }
}

__global__ void __launch_bounds__(NTHR, 1) ajrnn_kernel(
    const float* __restrict__ x,
    const float* __restrict__ k0, const float* __restrict__ r0, const float* __restrict__ b0,
    const float* __restrict__ k1, const float* __restrict__ r1, const float* __restrict__ b1,
    const float* __restrict__ Wm, const float* __restrict__ bias,
    float* __restrict__ out)
{
    extern __shared__ char smem[];
    const uint32_t smb = smem_u32(smem);
    const int tid = threadIdx.x;
    const int bid = blockIdx.x;
    const int n0  = bid * 4;
    const int dcol = bid >> 1;
    const int wid = tid >> 5, lane = tid & 31;
    float* sh_wp = (float*)(smem + SM_WP);

    // ---- weights: fp32 -> bf16 hi/lo, gate-interleaved col order ----
    unsigned short* w1h = (unsigned short*)(smem + SM_W1HI);
    unsigned short* w1l = (unsigned short*)(smem + SM_W1LO);
    unsigned short* w2h = (unsigned short*)(smem + SM_W2HI);
    unsigned short* w2l = (unsigned short*)(smem + SM_W2LO);
    for (int idx = tid; idx < 16*576; idx += NTHR) {
        int p = idx & 15, k = idx >> 4;
        int col = (2*(p>>3) + (p&1))*HH + n0 + ((p&7)>>1);
        float w = (k < DD) ? k0[k*2048 + col] : r0[(k-DD)*2048 + col];
        unsigned short hb, lb; bf16split(w, hb, lb);
        w1h[p*W1_STRIDE + k] = hb;
        w1l[p*W1_STRIDE + k] = lb;
    }
    for (int idx = tid; idx < 16*1024; idx += NTHR) {
        int p = idx & 15, k = idx >> 4;
        int col = (2*(p>>3) + (p&1))*HH + n0 + ((p&7)>>1);
        float w = (k < HH) ? k1[k*2048 + col] : r1[(k-HH)*2048 + col];
        unsigned short hb, lb; bf16split(w, hb, lb);
        w2h[p*W2_STRIDE + k] = hb;
        w2l[p*W2_STRIDE + k] = lb;
    }
    for (int i = tid; i < 512; i += NTHR) sh_wp[i] = Wm[i*DD + dcol];
    #pragma unroll
    for (int i = 0; i < 2; i++) {
        int g = i*(NBLK*NTHR) + bid*NTHR + tid;
        g_h1h[0][g] = 0; g_h1l[0][g] = 0;
        g_h2h[0][g] = 0; g_h2l[0][g] = 0;
        g_h2f[0][g] = 0.f;
    }
    if (tid < 64) {
        int r = (bid & 1)*64 + tid;
        float cv = x[(r*TT)*DD + dcol];
        unsigned short chi, clo; bf16split(cv, chi, clo);
        int ci = cfrag_idx(r, dcol);
        g_curh[ci] = chi; g_curl[ci] = clo;
    }
    if (tid == 0) atomicAdd(&g_cntA, 1);
    const float biasd = bias[dcol];

    const int jj = lane & 3;
    const float bi0 = b0[0*HH + n0 + jj], bf0 = b0[1*HH + n0 + jj];
    const float bg0 = b0[2*HH + n0 + jj], bo0 = b0[3*HH + n0 + jj];
    const float bi1 = b1[0*HH + n0 + jj], bf1 = b1[1*HH + n0 + jj];
    const float bg1 = b1[2*HH + n0 + jj], bo1 = b1[3*HH + n0 + jj];

    const int rowgrp = wid;
    const int crow = rowgrp*16 + (lane >> 2);
    const int bn  = (lane & 7) | ((lane >> 1) & 8);
    const int bk8 = (lane >> 3) & 1;
    const uint32_t b1hA  = smb + SM_W1HI + bn*(W1_STRIDE*2) + bk8*16;
    const uint32_t b1loA = smb + SM_W1LO + bn*(W1_STRIDE*2) + bk8*16;
    const uint32_t b2hA  = smb + SM_W2HI + bn*(W2_STRIDE*2) + bk8*16;
    const uint32_t b2loA = smb + SM_W2LO + bn*(W2_STRIDE*2) + bk8*16;

    grid_barrier();   // init + cur(0) visible; cntA == 128

    uint4 Ahi[2][4], Alo[2][4];          // 2-slot ring, slot = c & 1
    float c1st[2] = {0.f, 0.f}, c2st[2] = {0.f, 0.f};

    // prologue: chunks 0 (slot 0) and 1 (slot 1) of step 0 (h1old = zeros, parity 0)
    issue_chunk(Ahi[0], Alo[0], g_h1h[0], g_h1l[0], 32, 0, rowgrp, lane);
    issue_chunk(Ahi[1], Alo[1], g_h1h[0], g_h1l[0], 32, 4, rowgrp, lane);

    for (int t = 0; t < TT; t++) {
        const int rb = t & 1, wb = rb ^ 1;
        const unsigned short *h1r_h = g_h1h[rb], *h1r_l = g_h1l[rb];
        const unsigned short *h2r_h = g_h2h[rb], *h2r_l = g_h2l[rb];
        unsigned short *h1w_h = g_h1h[wb], *h1w_l = g_h1l[wb];
        unsigned short *h2w_h = g_h2h[wb], *h2w_l = g_h2l[wb];
        float B0h[4]={0,0,0,0}, B0l[4]={0,0,0,0}, B1h[4]={0,0,0,0}, B1l[4]={0,0,0,0};
        float D0h[4]={0,0,0,0}, D0l[4]={0,0,0,0}, D1h[4]={0,0,0,0}, D1l[4]={0,0,0,0};

        #pragma unroll
        for (int c = 0; c < 25; c++) {
            const int s = c & 1;
            // ---- compute chunk c from slot s ----
            if (c <= 7)
                compute_chunk(B0h,B0l,B1h,B1l, Ahi[s], Alo[s], b1hA + (64 + c*64)*2, b1loA + (64 + c*64)*2);
            else if (c <= 15)
                compute_chunk(D0h,D0l,D1h,D1l, Ahi[s], Alo[s], b2hA + (512 + (c-8)*64)*2, b2loA + (512 + (c-8)*64)*2);
            else if (c == 16)
                compute_chunk(B0h,B0l,B1h,B1l, Ahi[s], Alo[s], b1hA, b1loA);
            else
                compute_chunk(D0h,D0l,D1h,D1l, Ahi[s], Alo[s], b2hA + ((c-17)*64)*2, b2loA + ((c-17)*64)*2);

            // ---- gates + issue (target slot s, just freed by this compute) ----
            if (c <= 5) {
                // issue chunk c+2 in [2..7]: h1old
                issue_chunk(Ahi[s], Alo[s], h1r_h, h1r_l, 32, (c+2)*4, rowgrp, lane);
            } else if (c <= 13) {
                // issue chunk c+2 in [8..15]: h2old (gate once at c==6)
                if (c == 6) poll_cnt(&g_cntC, 128*t);
                issue_chunk(Ahi[s], Alo[s], h2r_h, h2r_l, 32, (c+2-8)*4, rowgrp, lane);
                if (c == 13 && t > 0) {
                    // Phase A(t): pred + impute cur(t) (h2f(t-1) gated by cntC at c==6)
                    const int r  = (bid & 1)*64 + (tid >> 2);
                    const int l4 = tid & 3;
                    const float* hrow = &g_h2f[rb][r*HH + l4*128];
                    const float* wv = sh_wp + l4*128;
                    float sacc = 0.f;
                    #pragma unroll
                    for (int kk = 0; kk < 128; kk += 4) {
                        float4 h4 = __ldcg((const float4*)(hrow + kk));
                        sacc += h4.x*wv[kk] + h4.y*wv[kk+1] + h4.z*wv[kk+2] + h4.w*wv[kk+3];
                    }
                    sacc += __shfl_xor_sync(0xffffffffu, sacc, 2);
                    sacc += __shfl_xor_sync(0xffffffffu, sacc, 1);
                    if (l4 == 0) {
                        float p  = sacc + biasd;
                        float xv = x[(r*TT + t)*DD + dcol];
                        float cv = (xv == 128.0f) ? p : xv;
                        unsigned short chi, clo; bf16split(cv, chi, clo);
                        int ci = cfrag_idx(r, dcol);
                        g_curh[ci] = chi; g_curl[ci] = clo;
                        out[(r*(TT-1) + (t-1))*DD + dcol] = p;
                    }
                    __syncthreads();
                    if (tid == 0) { __threadfence(); atomicAdd(&g_cntA, 1); }
                }
            } else if (c == 14) {
                poll_cnt(&g_cntA, 128*(t+1));
                issue_chunk(Ahi[0], Alo[0], g_curh, g_curl, 4, 0, rowgrp, lane);   // chunk 16 -> slot 0
            } else if (c == 16) {
                // ---- B epilogue: h1(t) ----
                float C0[4], C1[4];
                #pragma unroll
                for (int q = 0; q < 4; q++) { C0[q] = B0h[q] + B0l[q]; C1[q] = B1h[q] + B1l[q]; }
                float hout[2];
                gates2(C0, C1, bi0, bf0, bg0, bo0, c1st, hout);
                #pragma unroll
                for (int h = 0; h < 2; h++) {
                    int r = crow + 8*h;
                    unsigned short hi, lo; bf16split(hout[h], hi, lo);
                    int p = hfrag_idx(r, n0 + jj);
                    h1w_h[p] = hi; h1w_l[p] = lo;
                }
                __syncthreads();
                if (tid == 0) { __threadfence(); atomicAdd(&g_cntB, 1); }
                poll_cnt(&g_cntB, 128*(t+1));
                issue_chunk(Ahi[1], Alo[1], h1w_h, h1w_l, 32, 0*4, rowgrp, lane); // 17 -> slot 1
                issue_chunk(Ahi[0], Alo[0], h1w_h, h1w_l, 32, 1*4, rowgrp, lane); // 18 -> slot 0
            } else if (c >= 17 && c <= 22) {
                // issue chunk c+2 in [19..24]: h1new
                issue_chunk(Ahi[s], Alo[s], h1w_h, h1w_l, 32, (c+2-17)*4, rowgrp, lane);
            } else if (c == 24) {
                // issue next-step chunks 0 (slot 0) and 1 (slot 1): h1old(t+1) = h1(t)
                if (t + 1 < TT) {
                    issue_chunk(Ahi[0], Alo[0], h1w_h, h1w_l, 32, 0*4, rowgrp, lane);
                    issue_chunk(Ahi[1], Alo[1], h1w_h, h1w_l, 32, 1*4, rowgrp, lane);
                }
            }
            // c == 15, 23: no issue
        }

        // ---- C epilogue: h2(t) ----
        {
            float C0[4], C1[4];
            #pragma unroll
            for (int q = 0; q < 4; q++) { C0[q] = D0h[q] + D0l[q]; C1[q] = D1h[q] + D1l[q]; }
            float hout[2];
            gates2(C0, C1, bi1, bf1, bg1, bo1, c2st, hout);
            #pragma unroll
            for (int h = 0; h < 2; h++) {
                int r = crow + 8*h;
                unsigned short hi, lo; bf16split(hout[h], hi, lo);
                int p = hfrag_idx(r, n0 + jj);
                h2w_h[p] = hi; h2w_l[p] = lo;
                g_h2f[wb][r*HH + n0 + jj] = hout[h];
                if (t == TT-1) out[PRED_SZ + r*HH + n0 + jj] = hout[h];
            }
            __syncthreads();
            if (tid == 0) { __threadfence(); atomicAdd(&g_cntC, 1); }
        }
    }

    grid_barrier();
    if (bid == 0 && tid == 0) { g_cntA = 0; g_cntB = 0; g_cntC = 0; }
}

extern "C" void kernel_launch(void* const* d_in, const int* in_sizes, int n_in,
                              void* d_out, int out_size) {
    (void)in_sizes; (void)n_in; (void)out_size;
    const float* x    = (const float*)d_in[0];
    const float* k0   = (const float*)d_in[1];
    const float* r0   = (const float*)d_in[2];
    const float* b0   = (const float*)d_in[3];
    const float* k1   = (const float*)d_in[4];
    const float* r1   = (const float*)d_in[5];
    const float* b1   = (const float*)d_in[6];
    const float* Wm   = (const float*)d_in[7];
    const float* bias = (const float*)d_in[8];
    cudaFuncSetAttribute(ajrnn_kernel, cudaFuncAttributeMaxDynamicSharedMemorySize, SM_TOTAL);
    ajrnn_kernel<<<NBLK, NTHR, SM_TOTAL>>>(x, k0, r0, b0, k1, r1, b1, Wm, bias, (float*)d_out);
}